// round 11
// baseline (speedup 1.0000x reference)
#include <cuda_runtime.h>
#include <math.h>
#include <cstdint>

// Problem constants
#define BB    8
#define CC    128
#define HIN   62
#define HH    64
#define WW    64
#define GG    4
#define GCC   32
#define PP    9
#define NPOS  (BB*HH*WW)   // 32768

// Scratch (device globals; no allocation allowed)
__device__ float g_xt[NPOS*CC];
__device__ float g_y[NPOS*CC];
__device__ float g_xproj[NPOS*CC];
__device__ float g_om[NPOS*CC];      // fused offset(72)+mask-logits(36)+pad
__device__ float g_w1T[CC*CC];
__device__ float g_w2P[CC*CC];
__device__ float g_w3T[CC*CC];
__device__ float g_b2[CC];

// ===========================================================================
__device__ __forceinline__ uint32_t f2tf32(float f) {
    uint32_t r;
    asm("cvt.rna.tf32.f32 %0, %1;" : "=r"(r) : "f"(f));
    return r;
}
__device__ __forceinline__ void mma_tf32(float* c, const uint32_t* a, const uint32_t* b) {
    asm volatile(
        "mma.sync.aligned.m16n8k8.row.col.f32.tf32.tf32.f32 "
        "{%0,%1,%2,%3}, {%4,%5,%6,%7}, {%8,%9}, {%0,%1,%2,%3};"
        : "+f"(c[0]), "+f"(c[1]), "+f"(c[2]), "+f"(c[3])
        : "r"(a[0]), "r"(a[1]), "r"(a[2]), "r"(a[3]), "r"(b[0]), "r"(b[1]));
}
__device__ __forceinline__ uint32_t smem_u32(const void* p) {
    uint32_t a;
    asm("{ .reg .u64 t; cvta.to.shared.u64 t, %1; cvt.u32.u64 %0, t; }" : "=r"(a) : "l"(p));
    return a;
}
#define CP_ASYNC16(dst, src) \
    asm volatile("cp.async.cg.shared.global [%0], [%1], 16;" \
        :: "r"(dst), "l"(__cvta_generic_to_global(src)) : "memory")
#define CP_COMMIT() asm volatile("cp.async.commit_group;" ::: "memory")
#define CP_WAIT(n)  asm volatile("cp.async.wait_group %0;" :: "n"(n) : "memory")

// ===========================================================================
// Weight prep
// ===========================================================================
__global__ void prep_weights_kernel(const float* __restrict__ w1, const float* __restrict__ w3,
                                    const float* __restrict__ offw, const float* __restrict__ maskw,
                                    const float* __restrict__ offb, const float* __restrict__ maskb,
                                    float* __restrict__ w1T, float* __restrict__ w3T,
                                    float* __restrict__ w2P, float* __restrict__ b2) {
    const int n = blockIdx.x, k = threadIdx.x;
    w1T[n * CC + k] = w1[k * CC + n];
    w3T[n * CC + k] = w3[k * CC + n];
    float v = 0.f;
    if (n < 72)       v = offw[k * 72 + n];
    else if (n < 108) v = maskw[k * 36 + (n - 72)];
    w2P[n * CC + k] = v;
    if (k == 0) b2[n] = (n < 72) ? offb[n] : ((n < 108) ? maskb[n - 72] : 0.f);
}

// ===========================================================================
// x NCHW -> NHWC with 1-px zero border
// ===========================================================================
__global__ void pack_x_kernel(const float* __restrict__ x, float* __restrict__ xt) {
    __shared__ float t[32][33];
    const int b  = blockIdx.z >> 6;
    const int h  = blockIdx.z & 63;
    const int w0 = blockIdx.x * 32;
    const int c0 = blockIdx.y * 32;
    const int tx = threadIdx.x, ty = threadIdx.y;
    const int hh = h - 1;
    const int ww = w0 + tx - 1;
    const int cc = c0 + ty;
    float v = 0.f;
    if (hh >= 0 && hh < HIN && ww >= 0 && ww < HIN)
        v = x[(((size_t)b * CC + cc) * HIN + hh) * HIN + ww];
    t[ty][tx] = v;
    __syncthreads();
    xt[(((size_t)b * HH + h) * WW + (w0 + ty)) * CC + (c0 + tx)] = t[tx][ty];
}

// ===========================================================================
// Plain HMMA tf32 GEMM (conv1x1, in_proj): M64 x N64 tiles, double-buffered K.
// ===========================================================================
#define CH      64
#define CPITCH  68
#define STAGE_F (128 * CPITCH)
#define GEMM_SMEM (2 * STAGE_F * 4)

__global__ void __launch_bounds__(256, 3)
hmma_gemm_kernel(const float* __restrict__ A, const float* __restrict__ Bm,
                 const float* __restrict__ bias, float* __restrict__ Cout) {
    extern __shared__ float smem[];
    const uint32_t sbase = smem_u32(smem);

    const int tid  = threadIdx.x;
    const int lane = tid & 31;
    const int wid  = tid >> 5;
    const int gid  = lane >> 2;
    const int tg   = lane & 3;
    const int warp_m = wid & 3;
    const int warp_n = wid >> 2;
    const int m0 = blockIdx.x * 64;
    const int n0 = blockIdx.y * 64;

    const int irow = tid >> 4;
    const int ic   = (tid & 15) * 4;
    auto issue = [&](int s, int kc) {
        const uint32_t st = sbase + (uint32_t)(s * STAGE_F * 4);
        #pragma unroll
        for (int i = 0; i < 4; i++) {
            const int row = irow + i * 16;
            CP_ASYNC16(st + (uint32_t)((row * CPITCH + ic) * 4),
                       A + (size_t)(m0 + row) * CC + kc + ic);
        }
        #pragma unroll
        for (int i = 0; i < 4; i++) {
            const int row = irow + i * 16;
            CP_ASYNC16(st + (uint32_t)(((64 + row) * CPITCH + ic) * 4),
                       Bm + (size_t)(n0 + row) * CC + kc + ic);
        }
        CP_COMMIT();
    };

    issue(0, 0);
    issue(1, CH);

    float acc[4][4];
    #pragma unroll
    for (int ni = 0; ni < 4; ni++)
        #pragma unroll
        for (int j = 0; j < 4; j++) acc[ni][j] = 0.f;

    const int arow0 = warp_m * 16 + gid;
    const int bcol0 = warp_n * 32 + gid;

    auto mma_chunk = [&](int s) {
        const float* uA = smem + s * STAGE_F;
        const float* uB = uA + 64 * CPITCH;
        #pragma unroll
        for (int ks = 0; ks < 8; ks++) {
            const int k8 = ks * 8;
            uint32_t af[4];
            af[0] = f2tf32(uA[(arow0    ) * CPITCH + k8 + tg]);
            af[1] = f2tf32(uA[(arow0 + 8) * CPITCH + k8 + tg]);
            af[2] = f2tf32(uA[(arow0    ) * CPITCH + k8 + tg + 4]);
            af[3] = f2tf32(uA[(arow0 + 8) * CPITCH + k8 + tg + 4]);
            #pragma unroll
            for (int ni = 0; ni < 4; ni++) {
                const int n = bcol0 + ni * 8;
                uint32_t bf[2];
                bf[0] = f2tf32(uB[n * CPITCH + k8 + tg]);
                bf[1] = f2tf32(uB[n * CPITCH + k8 + tg + 4]);
                mma_tf32(acc[ni], af, bf);
            }
        }
    };

    CP_WAIT(1);
    __syncthreads();
    mma_chunk(0);
    CP_WAIT(0);
    __syncthreads();
    mma_chunk(1);

    const int r0 = m0 + arow0;
    #pragma unroll
    for (int ni = 0; ni < 4; ni++) {
        const int col = n0 + warp_n * 32 + ni * 8 + 2 * tg;
        const float bx = __ldg(bias + col);
        const float by = __ldg(bias + col + 1);
        float2 v0 = make_float2(acc[ni][0] + bx, acc[ni][1] + by);
        float2 v1 = make_float2(acc[ni][2] + bx, acc[ni][3] + by);
        *reinterpret_cast<float2*>(Cout + (size_t)r0 * CC + col)       = v0;
        *reinterpret_cast<float2*>(Cout + (size_t)(r0 + 8) * CC + col) = v1;
    }
}

// ===========================================================================
// Fused kernels share this layout: M64 x N128 x K128 GEMM.
//   smem floats: A(tf32 uints) [64][132], B [128][132], extra region.
// A is produced in-kernel (dw+LN+GELU, or sampler); B prefetched via cp.async.
// ===========================================================================
#define FPITCH  132
#define FA_F    (64 * FPITCH)     // 8448 floats
#define FB_F    (128 * FPITCH)    // 16896 floats
#define FB_OFF  FA_F
#define FX_OFF  (FA_F + FB_F)     // extra region (sW / sOM)
#define DWF_SMEM  ((FA_F + FB_F + 9 * CC) * 4)          // 105984 B
#define SPF_SMEM  ((FA_F + FB_F + 8 * 116) * 4)         // 105088 B

// ---- common device helpers for fused kernels ----
__device__ __forceinline__ void fused_issue_B(uint32_t sbase, const float* Bm, int tid) {
    #pragma unroll
    for (int i = 0; i < 16; i++) {
        const int idx = i * 256 + tid;
        const int row = idx >> 5;
        const int c4  = idx & 31;
        CP_ASYNC16(sbase + (uint32_t)((FB_OFF + row * FPITCH + c4 * 4) * 4),
                   Bm + (size_t)row * CC + c4 * 4);
    }
    CP_COMMIT();
}
__device__ __forceinline__ void fused_convert_B(float* smem, int tid) {
    // in-place fp32 -> tf32 bits on the 128x128 valid region
    uint32_t* uB = reinterpret_cast<uint32_t*>(smem + FB_OFF);
    #pragma unroll
    for (int i = 0; i < 64; i++) {
        const int idx = i * 256 + tid;
        const int off = (idx >> 7) * FPITCH + (idx & 127);
        uB[off] = f2tf32(__uint_as_float(uB[off]));
    }
}
// MMA M64xN128: acc[8][4] per thread; warp (4m x 2n), warp tile 16 x 64.
__device__ __forceinline__ void fused_mma(const float* smem, int arow0, int bcol0,
                                          int tg, float acc[8][4]) {
    const uint32_t* uA = reinterpret_cast<const uint32_t*>(smem);
    const uint32_t* uB = reinterpret_cast<const uint32_t*>(smem + FB_OFF);
    #pragma unroll
    for (int ks = 0; ks < 16; ks++) {
        const int k8 = ks * 8;
        uint32_t af[4];
        af[0] = uA[(arow0    ) * FPITCH + k8 + tg];
        af[1] = uA[(arow0 + 8) * FPITCH + k8 + tg];
        af[2] = uA[(arow0    ) * FPITCH + k8 + tg + 4];
        af[3] = uA[(arow0 + 8) * FPITCH + k8 + tg + 4];
        #pragma unroll
        for (int ni = 0; ni < 8; ni++) {
            const int n = bcol0 + ni * 8;
            uint32_t bf[2];
            bf[0] = uB[n * FPITCH + k8 + tg];
            bf[1] = uB[n * FPITCH + k8 + tg + 4];
            mma_tf32(acc[ni], af, bf);
        }
    }
}

// ===========================================================================
// Fused dw3x3 + LN + GELU  ->  off/mask GEMM (N=128 padded). Tile = 64 pos
// = one (b,h) image row. Output om NHWC-style [pos][128].
// ===========================================================================
__global__ void __launch_bounds__(256, 2)
dwoff_gemm_kernel(const float* __restrict__ y,
                  const float* __restrict__ dww, const float* __restrict__ dwb,
                  const float* __restrict__ lng, const float* __restrict__ lnb,
                  const float* __restrict__ Bm, const float* __restrict__ bias,
                  float* __restrict__ Cout) {
    extern __shared__ float smem[];
    const uint32_t sbase = smem_u32(smem);
    const int tid  = threadIdx.x;
    const int lane = tid & 31;
    const int wid  = tid >> 5;
    const int m0   = blockIdx.x * 64;
    const int b = m0 >> 12;
    const int h = (m0 >> 6) & 63;

    fused_issue_B(sbase, Bm, tid);

    // stage dw weights transposed [tap][c]
    float* sW = smem + FX_OFF;
    for (int i = tid; i < 9 * CC; i += 256) {
        const int c = i / 9, tap = i % 9;
        sW[tap * CC + c] = dww[i];
    }
    __syncthreads();

    // dw + LN + GELU: 8 warps x 8 positions, lane = 4 channels -> sA tf32
    uint32_t* uA = reinterpret_cast<uint32_t*>(smem);
    const int c4 = lane * 4;
    const float4 bv    = __ldg(reinterpret_cast<const float4*>(dwb + c4));
    const float4 gv    = __ldg(reinterpret_cast<const float4*>(lng + c4));
    const float4 betav = __ldg(reinterpret_cast<const float4*>(lnb + c4));
    #pragma unroll
    for (int pp = 0; pp < 8; pp++) {
        const int pl = wid * 8 + pp;     // local pos 0..63 == w
        const int w  = pl;
        float4 acc = bv;
        const float* ybase = y + (((size_t)b * HH + h) * WW + w) * CC + c4;
        #pragma unroll
        for (int i = 0; i < 3; i++) {
            const int hh = h + i - 1;
            if ((unsigned)hh >= (unsigned)HH) continue;
            #pragma unroll
            for (int j = 0; j < 3; j++) {
                const int ww = w + j - 1;
                if ((unsigned)ww >= (unsigned)WW) continue;
                const float4 v = __ldg(reinterpret_cast<const float4*>(
                    ybase + ((i - 1) * WW + (j - 1)) * CC));
                const float4 wt = *reinterpret_cast<const float4*>(sW + (i * 3 + j) * CC + c4);
                acc.x = fmaf(v.x, wt.x, acc.x);
                acc.y = fmaf(v.y, wt.y, acc.y);
                acc.z = fmaf(v.z, wt.z, acc.z);
                acc.w = fmaf(v.w, wt.w, acc.w);
            }
        }
        float s  = acc.x + acc.y + acc.z + acc.w;
        float s2 = acc.x * acc.x + acc.y * acc.y + acc.z * acc.z + acc.w * acc.w;
        #pragma unroll
        for (int o = 16; o > 0; o >>= 1) {
            s  += __shfl_xor_sync(0xFFFFFFFFu, s,  o);
            s2 += __shfl_xor_sync(0xFFFFFFFFu, s2, o);
        }
        const float mean = s * (1.f / CC);
        const float var  = s2 * (1.f / CC) - mean * mean;
        const float rstd = rsqrtf(var + 1e-5f);
        const float kg = 0.70710678118654752440f;
        float v0 = (acc.x - mean) * rstd * gv.x + betav.x;
        float v1 = (acc.y - mean) * rstd * gv.y + betav.y;
        float v2 = (acc.z - mean) * rstd * gv.z + betav.z;
        float v3 = (acc.w - mean) * rstd * gv.w + betav.w;
        uint4 t;
        t.x = f2tf32(0.5f * v0 * (1.f + erff(v0 * kg)));
        t.y = f2tf32(0.5f * v1 * (1.f + erff(v1 * kg)));
        t.z = f2tf32(0.5f * v2 * (1.f + erff(v2 * kg)));
        t.w = f2tf32(0.5f * v3 * (1.f + erff(v3 * kg)));
        *reinterpret_cast<uint4*>(uA + pl * FPITCH + c4) = t;
    }

    CP_WAIT(0);
    __syncthreads();
    fused_convert_B(smem, tid);
    __syncthreads();

    float acc[8][4];
    #pragma unroll
    for (int ni = 0; ni < 8; ni++)
        #pragma unroll
        for (int j = 0; j < 4; j++) acc[ni][j] = 0.f;
    const int gid = lane >> 2, tg = lane & 3;
    const int arow0 = (wid & 3) * 16 + gid;
    const int bcol0 = (wid >> 2) * 64 + gid;
    fused_mma(smem, arow0, bcol0, tg, acc);

    const int r0 = m0 + arow0;
    #pragma unroll
    for (int ni = 0; ni < 8; ni++) {
        const int col = (wid >> 2) * 64 + ni * 8 + 2 * tg;
        const float bx = __ldg(bias + col);
        const float by = __ldg(bias + col + 1);
        float2 v0 = make_float2(acc[ni][0] + bx, acc[ni][1] + by);
        float2 v1 = make_float2(acc[ni][2] + bx, acc[ni][3] + by);
        *reinterpret_cast<float2*>(Cout + (size_t)r0 * CC + col)       = v0;
        *reinterpret_cast<float2*>(Cout + (size_t)(r0 + 8) * CC + col) = v1;
    }
}

// ===========================================================================
// Fused DCNv3 sampler (+ group softmax)  ->  out_proj GEMM -> NCHW output.
// ===========================================================================
__global__ void __launch_bounds__(256, 2)
sampout_gemm_kernel(const float* __restrict__ xproj,
                    const float* __restrict__ om,
                    const float* __restrict__ Bm, const float* __restrict__ bias,
                    float* __restrict__ Cout) {
    extern __shared__ float smem[];
    const uint32_t sbase = smem_u32(smem);
    const int tid  = threadIdx.x;
    const int lane = tid & 31;
    const int wid  = tid >> 5;
    const int m0   = blockIdx.x * 64;
    const int b = m0 >> 12;
    const int h = (m0 >> 6) & 63;

    fused_issue_B(sbase, Bm, tid);

    uint32_t* uA = reinterpret_cast<uint32_t*>(smem);
    float* sOM = smem + FX_OFF + wid * 116;
    const int g  = lane >> 3;
    const int c4 = (lane & 7) * 4;

    #pragma unroll
    for (int pp = 0; pp < 8; pp++) {
        const int pl  = wid * 8 + pp;
        const int pos = m0 + pl;
        const int w   = pl;
        // load om row (108 floats)
        #pragma unroll
        for (int r = 0; r < 4; r++) {
            const int i = r * 32 + lane;
            if (i < 108) sOM[i] = __ldg(om + (size_t)pos * CC + i);
        }
        __syncwarp();
        // group softmax
        const float* logit = sOM + 72 + g * 9;
        float mx = -1e30f;
        #pragma unroll
        for (int p = 0; p < 9; p++) mx = fmaxf(mx, logit[p]);
        float se = 0.f;
        float ex[9];
        #pragma unroll
        for (int p = 0; p < 9; p++) { ex[p] = expf(logit[p] - mx); se += ex[p]; }
        const float inv_se = 1.f / se;

        const float* base = xproj + (size_t)b * (HH * WW * CC) + g * GCC + c4;
        float4 acc = make_float4(0.f, 0.f, 0.f, 0.f);
        #pragma unroll
        for (int p = 0; p < PP; p++) {
            const int gp = g * 9 + p;
            const float fix = (float)(w + p / 3) + sOM[2 * gp];
            const float fiy = (float)(h + p % 3) + sOM[2 * gp + 1];
            const float x0f = floorf(fix), y0f = floorf(fiy);
            const float fx = fix - x0f, fy = fiy - y0f;
            const int x0 = (int)x0f, y0 = (int)y0f;
            const float m = ex[p] * inv_se;
            const bool xv0 = (x0 >= 1) && (x0 <= 64);
            const bool xv1 = (x0 >= 0) && (x0 <= 63);
            const bool yv0 = (y0 >= 1) && (y0 <= 64);
            const bool yv1 = (y0 >= 0) && (y0 <= 63);
            float4 v00 = make_float4(0,0,0,0), v10 = v00, v01 = v00, v11 = v00;
            if (yv0 && xv0) v00 = __ldg(reinterpret_cast<const float4*>(base + ((size_t)(y0 - 1) * WW + (x0 - 1)) * CC));
            if (yv0 && xv1) v10 = __ldg(reinterpret_cast<const float4*>(base + ((size_t)(y0 - 1) * WW + (x0    )) * CC));
            if (yv1 && xv0) v01 = __ldg(reinterpret_cast<const float4*>(base + ((size_t)(y0    ) * WW + (x0 - 1)) * CC));
            if (yv1 && xv1) v11 = __ldg(reinterpret_cast<const float4*>(base + ((size_t)(y0    ) * WW + (x0    )) * CC));
            const float w00 = (1.f - fx) * (1.f - fy) * m;
            const float w10 = fx * (1.f - fy) * m;
            const float w01 = (1.f - fx) * fy * m;
            const float w11 = fx * fy * m;
            acc.x += v00.x * w00 + v10.x * w10 + v01.x * w01 + v11.x * w11;
            acc.y += v00.y * w00 + v10.y * w10 + v01.y * w01 + v11.y * w11;
            acc.z += v00.z * w00 + v10.z * w10 + v01.z * w01 + v11.z * w11;
            acc.w += v00.w * w00 + v10.w * w10 + v01.w * w01 + v11.w * w11;
        }
        uint4 t;
        t.x = f2tf32(acc.x); t.y = f2tf32(acc.y);
        t.z = f2tf32(acc.z); t.w = f2tf32(acc.w);
        *reinterpret_cast<uint4*>(uA + pl * FPITCH + g * GCC + c4) = t;
        __syncwarp();
    }

    CP_WAIT(0);
    __syncthreads();
    fused_convert_B(smem, tid);
    __syncthreads();

    float acc[8][4];
    #pragma unroll
    for (int ni = 0; ni < 8; ni++)
        #pragma unroll
        for (int j = 0; j < 4; j++) acc[ni][j] = 0.f;
    const int gid = lane >> 2, tg = lane & 3;
    const int arow0 = (wid & 3) * 16 + gid;
    const int bcol0 = (wid >> 2) * 64 + gid;
    fused_mma(smem, arow0, bcol0, tg, acc);

    // NCHW epilogue: stage transposed [128 cols][64 rows], pitch 68, in B region.
    __syncthreads();
    float* sCT = smem + FB_OFF;
    #pragma unroll
    for (int ni = 0; ni < 8; ni++) {
        const int col = (wid >> 2) * 64 + ni * 8 + 2 * tg;
        const float bx = __ldg(bias + col);
        const float by = __ldg(bias + col + 1);
        sCT[(col    ) * 68 + arow0    ] = acc[ni][0] + bx;
        sCT[(col + 1) * 68 + arow0    ] = acc[ni][1] + by;
        sCT[(col    ) * 68 + arow0 + 8] = acc[ni][2] + bx;
        sCT[(col + 1) * 68 + arow0 + 8] = acc[ni][3] + by;
    }
    __syncthreads();
    const int inbatch = m0 & 4095;
    #pragma unroll
    for (int i = 0; i < 8; i++) {
        const int idx = i * 256 + tid;     // 2048 float4s: 128 cols x 16
        const int col = idx >> 4;
        const int rc  = idx & 15;
        const float4 v = *reinterpret_cast<const float4*>(sCT + col * 68 + rc * 4);
        *reinterpret_cast<float4*>(
            Cout + ((size_t)b * CC + col) * (HH * WW) + inbatch + rc * 4) = v;
    }
}

// ===========================================================================
extern "C" void kernel_launch(void* const* d_in, const int* in_sizes, int n_in,
                              void* d_out, int out_size) {
    const float* x         = (const float*)d_in[0];
    const float* conv_w    = (const float*)d_in[1];
    const float* conv_b    = (const float*)d_in[2];
    const float* in_proj_w = (const float*)d_in[3];
    const float* in_proj_b = (const float*)d_in[4];
    const float* dw_w      = (const float*)d_in[5];
    const float* dw_b      = (const float*)d_in[6];
    const float* ln_g      = (const float*)d_in[7];
    const float* ln_b      = (const float*)d_in[8];
    const float* off_w     = (const float*)d_in[9];
    const float* off_b     = (const float*)d_in[10];
    const float* mask_w    = (const float*)d_in[11];
    const float* mask_b    = (const float*)d_in[12];
    const float* out_w     = (const float*)d_in[13];
    const float* out_b     = (const float*)d_in[14];
    float* out = (float*)d_out;

    float *xt, *y, *xproj, *omp, *w1T, *w2P, *w3T, *b2;
    cudaGetSymbolAddress((void**)&xt,    g_xt);
    cudaGetSymbolAddress((void**)&y,     g_y);
    cudaGetSymbolAddress((void**)&xproj, g_xproj);
    cudaGetSymbolAddress((void**)&omp,   g_om);
    cudaGetSymbolAddress((void**)&w1T,   g_w1T);
    cudaGetSymbolAddress((void**)&w2P,   g_w2P);
    cudaGetSymbolAddress((void**)&w3T,   g_w3T);
    cudaGetSymbolAddress((void**)&b2,    g_b2);

    static cudaStream_t s1 = nullptr;
    static cudaEvent_t eFork = nullptr, ePrep = nullptr, eConv = nullptr, eProj = nullptr;
    static bool init_done = false;
    if (!init_done) {
        cudaFuncSetAttribute(hmma_gemm_kernel,
                             cudaFuncAttributeMaxDynamicSharedMemorySize, GEMM_SMEM);
        cudaFuncSetAttribute(dwoff_gemm_kernel,
                             cudaFuncAttributeMaxDynamicSharedMemorySize, DWF_SMEM);
        cudaFuncSetAttribute(sampout_gemm_kernel,
                             cudaFuncAttributeMaxDynamicSharedMemorySize, SPF_SMEM);
        cudaStreamCreateWithFlags(&s1, cudaStreamNonBlocking);
        cudaEventCreateWithFlags(&eFork, cudaEventDisableTiming);
        cudaEventCreateWithFlags(&ePrep, cudaEventDisableTiming);
        cudaEventCreateWithFlags(&eConv, cudaEventDisableTiming);
        cudaEventCreateWithFlags(&eProj, cudaEventDisableTiming);
        init_done = true;
    }

    const dim3 tblk(32, 32);
    const dim3 tgrid(2, 4, BB * HH);
    const dim3 ggrid(NPOS / 64, 2);

    // ---- fork side stream ----
    cudaEventRecord(eFork, 0);
    cudaStreamWaitEvent(s1, eFork, 0);

    // s1: weight prep
    prep_weights_kernel<<<CC, CC, 0, s1>>>(in_proj_w, out_w, off_w, mask_w, off_b, mask_b,
                                           w1T, w3T, w2P, b2);
    cudaEventRecord(ePrep, s1);

    // s0: pack + conv
    pack_x_kernel<<<tgrid, tblk>>>(x, xt);
    hmma_gemm_kernel<<<ggrid, 256, GEMM_SMEM>>>(xt, conv_w, conv_b, y);
    cudaEventRecord(eConv, 0);

    // s1: in_proj (parallel with fused dw branch)
    cudaStreamWaitEvent(s1, eConv, 0);
    hmma_gemm_kernel<<<ggrid, 256, GEMM_SMEM, s1>>>(y, w1T, in_proj_b, xproj);
    cudaEventRecord(eProj, s1);

    // s0: fused dw+LN+GELU -> off/mask GEMM
    cudaStreamWaitEvent(0, ePrep, 0);
    dwoff_gemm_kernel<<<NPOS / 64, 256, DWF_SMEM>>>(y, dw_w, dw_b, ln_g, ln_b,
                                                    w2P, b2, omp);

    // join; s0: fused sampler -> out_proj -> NCHW
    cudaStreamWaitEvent(0, eProj, 0);
    sampout_gemm_kernel<<<NPOS / 64, 256, SPF_SMEM>>>(xproj, omp, w3T, out_b, out);
}

// round 12
// speedup vs baseline: 1.1947x; 1.1947x over previous
#include <cuda_runtime.h>
#include <math.h>
#include <cstdint>

// Problem constants
#define BB    8
#define CC    128
#define HIN   62
#define HH    64
#define WW    64
#define GG    4
#define GCC   32
#define PP    9
#define NPOS  (BB*HH*WW)   // 32768

// Scratch (device globals; no allocation allowed)
__device__ float g_xt[NPOS*CC];
__device__ float g_y[NPOS*CC];
__device__ float g_xproj[NPOS*CC];
__device__ float g_dg[NPOS*CC];
__device__ float g_samp[NPOS*CC];
__device__ float g_om[NPOS*CC];
__device__ float g_w1T[CC*CC];
__device__ float g_w2P[CC*CC];
__device__ float g_w3T[CC*CC];
__device__ float g_b2[CC];

// ===========================================================================
__device__ __forceinline__ uint32_t f2tf32(float f) {
    uint32_t r;
    asm("cvt.rna.tf32.f32 %0, %1;" : "=r"(r) : "f"(f));
    return r;
}
__device__ __forceinline__ void mma_tf32(float* c, const uint32_t* a, const uint32_t* b) {
    asm volatile(
        "mma.sync.aligned.m16n8k8.row.col.f32.tf32.tf32.f32 "
        "{%0,%1,%2,%3}, {%4,%5,%6,%7}, {%8,%9}, {%0,%1,%2,%3};"
        : "+f"(c[0]), "+f"(c[1]), "+f"(c[2]), "+f"(c[3])
        : "r"(a[0]), "r"(a[1]), "r"(a[2]), "r"(a[3]), "r"(b[0]), "r"(b[1]));
}
__device__ __forceinline__ uint32_t smem_u32(const void* p) {
    uint32_t a;
    asm("{ .reg .u64 t; cvta.to.shared.u64 t, %1; cvt.u32.u64 %0, t; }" : "=r"(a) : "l"(p));
    return a;
}
#define CP_ASYNC16(dst, src) \
    asm volatile("cp.async.cg.shared.global [%0], [%1], 16;" \
        :: "r"(dst), "l"(__cvta_generic_to_global(src)) : "memory")
#define CP_COMMIT() asm volatile("cp.async.commit_group;" ::: "memory")
#define CP_WAIT(n)  asm volatile("cp.async.wait_group %0;" :: "n"(n) : "memory")

// ===========================================================================
// Weight prep
// ===========================================================================
__global__ void prep_weights_kernel(const float* __restrict__ w1, const float* __restrict__ w3,
                                    const float* __restrict__ offw, const float* __restrict__ maskw,
                                    const float* __restrict__ offb, const float* __restrict__ maskb,
                                    float* __restrict__ w1T, float* __restrict__ w3T,
                                    float* __restrict__ w2P, float* __restrict__ b2) {
    const int n = blockIdx.x, k = threadIdx.x;
    w1T[n * CC + k] = w1[k * CC + n];
    w3T[n * CC + k] = w3[k * CC + n];
    float v = 0.f;
    if (n < 72)       v = offw[k * 72 + n];
    else if (n < 108) v = maskw[k * 36 + (n - 72)];
    w2P[n * CC + k] = v;
    if (k == 0) b2[n] = (n < 72) ? offb[n] : ((n < 108) ? maskb[n - 72] : 0.f);
}

// ===========================================================================
// x NCHW -> NHWC with 1-px zero border
// ===========================================================================
__global__ void pack_x_kernel(const float* __restrict__ x, float* __restrict__ xt) {
    __shared__ float t[32][33];
    const int b  = blockIdx.z >> 6;
    const int h  = blockIdx.z & 63;
    const int w0 = blockIdx.x * 32;
    const int c0 = blockIdx.y * 32;
    const int tx = threadIdx.x, ty = threadIdx.y;
    const int hh = h - 1;
    const int ww = w0 + tx - 1;
    const int cc = c0 + ty;
    float v = 0.f;
    if (hh >= 0 && hh < HIN && ww >= 0 && ww < HIN)
        v = x[(((size_t)b * CC + cc) * HIN + hh) * HIN + ww];
    t[ty][tx] = v;
    __syncthreads();
    xt[(((size_t)b * HH + h) * WW + (w0 + ty)) * CC + (c0 + tx)] = t[tx][ty];
}

// ===========================================================================
// HMMA tf32 GEMM, split-N + cp.async double-buffered K-chunks (R9 config).
// CTA = 256 threads (4m x 2n warps); tile = 128 rows x 64 cols; K chunk = 64.
// TO_NCHW=true: epilogue transposes through smem, writes NCHW directly.
// ===========================================================================
#define CH      64
#define CPITCH  68
#define STAGE_F (192 * CPITCH)
#define GEMM_SMEM (2 * STAGE_F * 4)       // 104448 bytes
#define SPITCH  132

template <bool TO_NCHW>
__global__ void __launch_bounds__(256, 2)
hmma_gemm_kernel(const float* __restrict__ A, const float* __restrict__ Bm,
                 const float* __restrict__ bias, float* __restrict__ Cout) {
    extern __shared__ float smem[];
    const uint32_t sbase = smem_u32(smem);

    const int tid  = threadIdx.x;
    const int lane = tid & 31;
    const int wid  = tid >> 5;
    const int gid  = lane >> 2;
    const int tg   = lane & 3;
    const int warp_m = wid & 3;
    const int warp_n = wid >> 2;
    const int m0 = blockIdx.x * 128;
    const int n0 = blockIdx.y * 64;

    const int irow_a = tid >> 4;
    const int ic     = (tid & 15) * 4;
    auto issue = [&](int s, int kc) {
        const uint32_t st = sbase + (uint32_t)(s * STAGE_F * 4);
        #pragma unroll
        for (int i = 0; i < 8; i++) {
            const int row = irow_a + i * 16;
            CP_ASYNC16(st + (uint32_t)((row * CPITCH + ic) * 4),
                       A + (size_t)(m0 + row) * CC + kc + ic);
        }
        #pragma unroll
        for (int i = 0; i < 4; i++) {
            const int row = irow_a + i * 16;
            if (row < 64) {
                CP_ASYNC16(st + (uint32_t)(((128 + row) * CPITCH + ic) * 4),
                           Bm + (size_t)(n0 + row) * CC + kc + ic);
            }
        }
        CP_COMMIT();
    };

    issue(0, 0);
    issue(1, CH);

    float acc[2][4][4];
    #pragma unroll
    for (int mi = 0; mi < 2; mi++)
        #pragma unroll
        for (int ni = 0; ni < 4; ni++)
            #pragma unroll
            for (int j = 0; j < 4; j++) acc[mi][ni][j] = 0.f;

    const int arow0 = warp_m * 32 + gid;
    const int bcol0 = warp_n * 32 + gid;

    auto mma_chunk = [&](int s) {
        const float* uA = smem + s * STAGE_F;
        const float* uB = uA + 128 * CPITCH;
        #pragma unroll
        for (int ks = 0; ks < 8; ks++) {
            const int k8 = ks * 8;
            uint32_t af[2][4];
            #pragma unroll
            for (int mi = 0; mi < 2; mi++) {
                const int r = arow0 + mi * 16;
                af[mi][0] = f2tf32(uA[(r    ) * CPITCH + k8 + tg]);
                af[mi][1] = f2tf32(uA[(r + 8) * CPITCH + k8 + tg]);
                af[mi][2] = f2tf32(uA[(r    ) * CPITCH + k8 + tg + 4]);
                af[mi][3] = f2tf32(uA[(r + 8) * CPITCH + k8 + tg + 4]);
            }
            #pragma unroll
            for (int ni = 0; ni < 4; ni++) {
                const int n = bcol0 + ni * 8;
                uint32_t bf[2];
                bf[0] = f2tf32(uB[n * CPITCH + k8 + tg]);
                bf[1] = f2tf32(uB[n * CPITCH + k8 + tg + 4]);
                mma_tf32(acc[0][ni], af[0], bf);
                mma_tf32(acc[1][ni], af[1], bf);
            }
        }
    };

    CP_WAIT(1);
    __syncthreads();
    mma_chunk(0);
    CP_WAIT(0);
    __syncthreads();
    mma_chunk(1);

    float2 bb[4];
    #pragma unroll
    for (int ni = 0; ni < 4; ni++) {
        const int col = n0 + warp_n * 32 + ni * 8 + 2 * tg;
        bb[ni].x = __ldg(bias + col);
        bb[ni].y = __ldg(bias + col + 1);
    }

    if (!TO_NCHW) {
        #pragma unroll
        for (int mi = 0; mi < 2; mi++) {
            const int r0 = m0 + arow0 + mi * 16;
            #pragma unroll
            for (int ni = 0; ni < 4; ni++) {
                const int col = n0 + warp_n * 32 + ni * 8 + 2 * tg;
                float2 v0 = make_float2(acc[mi][ni][0] + bb[ni].x, acc[mi][ni][1] + bb[ni].y);
                float2 v1 = make_float2(acc[mi][ni][2] + bb[ni].x, acc[mi][ni][3] + bb[ni].y);
                *reinterpret_cast<float2*>(Cout + (size_t)r0 * CC + col)       = v0;
                *reinterpret_cast<float2*>(Cout + (size_t)(r0 + 8) * CC + col) = v1;
            }
        }
    } else {
        __syncthreads();
        float* sCT = smem;  // [64 cols][128 rows], pitch 132
        #pragma unroll
        for (int mi = 0; mi < 2; mi++) {
            #pragma unroll
            for (int ni = 0; ni < 4; ni++) {
                const int col = warp_n * 32 + ni * 8 + 2 * tg;
                const int r   = arow0 + mi * 16;
                sCT[(col    ) * SPITCH + r    ] = acc[mi][ni][0] + bb[ni].x;
                sCT[(col + 1) * SPITCH + r    ] = acc[mi][ni][1] + bb[ni].y;
                sCT[(col    ) * SPITCH + r + 8] = acc[mi][ni][2] + bb[ni].x;
                sCT[(col + 1) * SPITCH + r + 8] = acc[mi][ni][3] + bb[ni].y;
            }
        }
        __syncthreads();
        const int b       = m0 >> 12;
        const int inbatch = m0 & 4095;
        #pragma unroll
        for (int i = 0; i < 8; i++) {
            const int idx = i * 256 + tid;
            const int col = idx >> 5;
            const int rc  = idx & 31;
            const float4 v = *reinterpret_cast<const float4*>(sCT + col * SPITCH + rc * 4);
            *reinterpret_cast<float4*>(
                Cout + ((size_t)b * CC + (n0 + col)) * (HH * WW) + inbatch + rc * 4) = v;
        }
    }
}

// ===========================================================================
// Depthwise 3x3 (pad 1) + bias + LayerNorm(C) + exact GELU.
// ===========================================================================
__global__ void __launch_bounds__(256)
dw_ln_gelu_kernel(const float* __restrict__ y,
                  const float* __restrict__ dww,
                  const float* __restrict__ dwb,
                  const float* __restrict__ lng,
                  const float* __restrict__ lnb,
                  float* __restrict__ out) {
    __shared__ float sW[9 * CC];
    const int tid = threadIdx.x;
    for (int i = tid; i < 9 * CC; i += 256) {
        const int c = i / 9, tap = i % 9;
        sW[tap * CC + c] = dww[i];
    }
    __syncthreads();

    const int wid  = tid >> 5;
    const int lane = tid & 31;
    const int pos  = blockIdx.x * 8 + wid;
    const int b = pos >> 12;
    const int h = (pos >> 6) & 63;
    const int w = pos & 63;
    const int c4 = lane * 4;

    const float4 bv = __ldg(reinterpret_cast<const float4*>(dwb + c4));
    float4 acc = bv;
    const float* ybase = y + (((size_t)b * HH + h) * WW + w) * CC + c4;
    #pragma unroll
    for (int i = 0; i < 3; i++) {
        const int hh = h + i - 1;
        if ((unsigned)hh >= (unsigned)HH) continue;
        #pragma unroll
        for (int j = 0; j < 3; j++) {
            const int ww = w + j - 1;
            if ((unsigned)ww >= (unsigned)WW) continue;
            const float4 v = __ldg(reinterpret_cast<const float4*>(
                ybase + ((i - 1) * WW + (j - 1)) * CC));
            const float4 wt = *reinterpret_cast<const float4*>(sW + (i * 3 + j) * CC + c4);
            acc.x = fmaf(v.x, wt.x, acc.x);
            acc.y = fmaf(v.y, wt.y, acc.y);
            acc.z = fmaf(v.z, wt.z, acc.z);
            acc.w = fmaf(v.w, wt.w, acc.w);
        }
    }

    float s  = acc.x + acc.y + acc.z + acc.w;
    float s2 = acc.x * acc.x + acc.y * acc.y + acc.z * acc.z + acc.w * acc.w;
    #pragma unroll
    for (int o = 16; o > 0; o >>= 1) {
        s  += __shfl_xor_sync(0xFFFFFFFFu, s,  o);
        s2 += __shfl_xor_sync(0xFFFFFFFFu, s2, o);
    }
    const float mean = s * (1.f / CC);
    const float var  = s2 * (1.f / CC) - mean * mean;
    const float rstd = rsqrtf(var + 1e-5f);

    const float4 gv = __ldg(reinterpret_cast<const float4*>(lng + c4));
    const float4 betav = __ldg(reinterpret_cast<const float4*>(lnb + c4));
    float4 o4;
    {
        float v0 = (acc.x - mean) * rstd * gv.x + betav.x;
        float v1 = (acc.y - mean) * rstd * gv.y + betav.y;
        float v2 = (acc.z - mean) * rstd * gv.z + betav.z;
        float v3 = (acc.w - mean) * rstd * gv.w + betav.w;
        const float k = 0.70710678118654752440f;
        o4.x = 0.5f * v0 * (1.f + erff(v0 * k));
        o4.y = 0.5f * v1 * (1.f + erff(v1 * k));
        o4.z = 0.5f * v2 * (1.f + erff(v2 * k));
        o4.w = 0.5f * v3 * (1.f + erff(v3 * k));
    }
    *reinterpret_cast<float4*>(out + (size_t)pos * CC + c4) = o4;
}

// ===========================================================================
// DCNv3 bilinear sampler + fused group softmax.
// Block = 256 threads = 8 warps = 8 CONSECUTIVE positions (better L1 reuse:
// adjacent positions sample overlapping 4x4 neighborhoods).
// ===========================================================================
__global__ void __launch_bounds__(256)
sampler_kernel(const float* __restrict__ xproj,
               const float* __restrict__ om,
               float* __restrict__ out) {
    __shared__ float sOM[8][112];
    const int tid  = threadIdx.x;
    const int wid  = tid >> 5;
    const int lane = tid & 31;
    const int pos  = blockIdx.x * 8 + wid;
    const int b = pos >> 12;
    const int h = (pos >> 6) & 63;
    const int w = pos & 63;
    const int g  = lane >> 3;
    const int c4 = (lane & 7) * 4;

    #pragma unroll
    for (int r = 0; r < 4; r++) {
        const int i = r * 32 + lane;
        if (i < 108) sOM[wid][i] = __ldg(om + (size_t)pos * CC + i);
    }
    __syncwarp();

    const float* logit = &sOM[wid][72 + g * 9];
    float mx = -1e30f;
    #pragma unroll
    for (int p = 0; p < 9; p++) mx = fmaxf(mx, logit[p]);
    float se = 0.f;
    float ex[9];
    #pragma unroll
    for (int p = 0; p < 9; p++) { ex[p] = expf(logit[p] - mx); se += ex[p]; }
    const float inv_se = 1.f / se;

    const float* base = xproj + (size_t)b * (HH * WW * CC) + g * GCC + c4;
    float4 acc = make_float4(0.f, 0.f, 0.f, 0.f);
    #pragma unroll
    for (int p = 0; p < PP; p++) {
        const int gp = g * 9 + p;
        const float fix = (float)(w + p / 3) + sOM[wid][2 * gp];
        const float fiy = (float)(h + p % 3) + sOM[wid][2 * gp + 1];
        const float x0f = floorf(fix), y0f = floorf(fiy);
        const float fx = fix - x0f, fy = fiy - y0f;
        const int x0 = (int)x0f, y0 = (int)y0f;
        const float m = ex[p] * inv_se;

        const bool xv0 = (x0 >= 1) && (x0 <= 64);
        const bool xv1 = (x0 >= 0) && (x0 <= 63);
        const bool yv0 = (y0 >= 1) && (y0 <= 64);
        const bool yv1 = (y0 >= 0) && (y0 <= 63);
        float4 v00 = make_float4(0,0,0,0), v10 = v00, v01 = v00, v11 = v00;
        if (yv0 && xv0) v00 = __ldg(reinterpret_cast<const float4*>(base + ((size_t)(y0 - 1) * WW + (x0 - 1)) * CC));
        if (yv0 && xv1) v10 = __ldg(reinterpret_cast<const float4*>(base + ((size_t)(y0 - 1) * WW + (x0    )) * CC));
        if (yv1 && xv0) v01 = __ldg(reinterpret_cast<const float4*>(base + ((size_t)(y0    ) * WW + (x0 - 1)) * CC));
        if (yv1 && xv1) v11 = __ldg(reinterpret_cast<const float4*>(base + ((size_t)(y0    ) * WW + (x0    )) * CC));

        const float w00 = (1.f - fx) * (1.f - fy) * m;
        const float w10 = fx * (1.f - fy) * m;
        const float w01 = (1.f - fx) * fy * m;
        const float w11 = fx * fy * m;
        acc.x += v00.x * w00 + v10.x * w10 + v01.x * w01 + v11.x * w11;
        acc.y += v00.y * w00 + v10.y * w10 + v01.y * w01 + v11.y * w11;
        acc.z += v00.z * w00 + v10.z * w10 + v01.z * w01 + v11.z * w11;
        acc.w += v00.w * w00 + v10.w * w10 + v01.w * w01 + v11.w * w11;
    }
    *reinterpret_cast<float4*>(out + (size_t)pos * CC + g * GCC + c4) = acc;
}

// ===========================================================================
extern "C" void kernel_launch(void* const* d_in, const int* in_sizes, int n_in,
                              void* d_out, int out_size) {
    const float* x         = (const float*)d_in[0];
    const float* conv_w    = (const float*)d_in[1];
    const float* conv_b    = (const float*)d_in[2];
    const float* in_proj_w = (const float*)d_in[3];
    const float* in_proj_b = (const float*)d_in[4];
    const float* dw_w      = (const float*)d_in[5];
    const float* dw_b      = (const float*)d_in[6];
    const float* ln_g      = (const float*)d_in[7];
    const float* ln_b      = (const float*)d_in[8];
    const float* off_w     = (const float*)d_in[9];
    const float* off_b     = (const float*)d_in[10];
    const float* mask_w    = (const float*)d_in[11];
    const float* mask_b    = (const float*)d_in[12];
    const float* out_w     = (const float*)d_in[13];
    const float* out_b     = (const float*)d_in[14];
    float* out = (float*)d_out;

    float *xt, *y, *xproj, *dg, *samp, *omp, *w1T, *w2P, *w3T, *b2;
    cudaGetSymbolAddress((void**)&xt,    g_xt);
    cudaGetSymbolAddress((void**)&y,     g_y);
    cudaGetSymbolAddress((void**)&xproj, g_xproj);
    cudaGetSymbolAddress((void**)&dg,    g_dg);
    cudaGetSymbolAddress((void**)&samp,  g_samp);
    cudaGetSymbolAddress((void**)&omp,   g_om);
    cudaGetSymbolAddress((void**)&w1T,   g_w1T);
    cudaGetSymbolAddress((void**)&w2P,   g_w2P);
    cudaGetSymbolAddress((void**)&w3T,   g_w3T);
    cudaGetSymbolAddress((void**)&b2,    g_b2);

    static cudaStream_t s1 = nullptr;
    static cudaEvent_t eFork = nullptr, ePrep = nullptr, eConv = nullptr, eProj = nullptr;
    static bool init_done = false;
    if (!init_done) {
        cudaFuncSetAttribute(hmma_gemm_kernel<false>,
                             cudaFuncAttributeMaxDynamicSharedMemorySize, GEMM_SMEM);
        cudaFuncSetAttribute(hmma_gemm_kernel<true>,
                             cudaFuncAttributeMaxDynamicSharedMemorySize, GEMM_SMEM);
        cudaStreamCreateWithFlags(&s1, cudaStreamNonBlocking);
        cudaEventCreateWithFlags(&eFork, cudaEventDisableTiming);
        cudaEventCreateWithFlags(&ePrep, cudaEventDisableTiming);
        cudaEventCreateWithFlags(&eConv, cudaEventDisableTiming);
        cudaEventCreateWithFlags(&eProj, cudaEventDisableTiming);
        init_done = true;
    }

    const dim3 tblk(32, 32);
    const dim3 tgrid(2, 4, BB * HH);
    const dim3 ggrid(NPOS / 128, 2);

    // ---- fork side stream ----
    cudaEventRecord(eFork, 0);
    cudaStreamWaitEvent(s1, eFork, 0);

    // s1: weight prep
    prep_weights_kernel<<<CC, CC, 0, s1>>>(in_proj_w, out_w, off_w, mask_w, off_b, mask_b,
                                           w1T, w3T, w2P, b2);
    cudaEventRecord(ePrep, s1);

    // s0: pack + conv
    pack_x_kernel<<<tgrid, tblk>>>(x, xt);
    hmma_gemm_kernel<false><<<ggrid, 256, GEMM_SMEM>>>(xt, conv_w, conv_b, y);
    cudaEventRecord(eConv, 0);

    // s1: in_proj (parallel with dw branch)
    cudaStreamWaitEvent(s1, eConv, 0);
    hmma_gemm_kernel<false><<<ggrid, 256, GEMM_SMEM, s1>>>(y, w1T, in_proj_b, xproj);
    cudaEventRecord(eProj, s1);

    // s0: dw+LN+GELU -> off_mask GEMM
    dw_ln_gelu_kernel<<<NPOS / 8, 256>>>(y, dw_w, dw_b, ln_g, ln_b, dg);
    cudaStreamWaitEvent(0, ePrep, 0);
    hmma_gemm_kernel<false><<<ggrid, 256, GEMM_SMEM>>>(dg, w2P, b2, omp);

    // join: sampler needs xproj (s1) + omp (s0)
    cudaStreamWaitEvent(0, eProj, 0);
    sampler_kernel<<<NPOS / 8, 256>>>(xproj, omp, samp);

    // out_proj writes NCHW directly
    hmma_gemm_kernel<true><<<ggrid, 256, GEMM_SMEM>>>(samp, w3T, out_b, out);
}

// round 13
// speedup vs baseline: 1.2142x; 1.0164x over previous
#include <cuda_runtime.h>
#include <math.h>
#include <cstdint>

// Problem constants
#define BB    8
#define CC    128
#define HIN   62
#define HH    64
#define WW    64
#define GG    4
#define GCC   32
#define PP    9
#define NPOS  (BB*HH*WW)   // 32768

// Scratch (device globals; no allocation allowed)
__device__ float g_xt[NPOS*CC];      // tf32-rounded
__device__ float g_y[NPOS*CC];       // tf32-rounded
__device__ float g_xproj[NPOS*CC];   // full fp32 (sampler input)
__device__ float g_dg[NPOS*CC];      // tf32-rounded
__device__ float g_samp[NPOS*CC];    // tf32-rounded
__device__ float g_om[NPOS*CC];      // full fp32 (sampler input)
__device__ float g_w0R[CC*CC];       // conv_w rounded [n][k]
__device__ float g_w1T[CC*CC];       // in_proj_w transposed+rounded [n][k]
__device__ float g_w2P[CC*CC];       // off/mask fused, padded, rounded
__device__ float g_w3T[CC*CC];       // out_proj_w transposed+rounded
__device__ float g_b2[CC];

// ===========================================================================
__device__ __forceinline__ uint32_t f2tf32(float f) {
    uint32_t r;
    asm("cvt.rna.tf32.f32 %0, %1;" : "=r"(r) : "f"(f));
    return r;
}
__device__ __forceinline__ float tf32r(float f) { return __uint_as_float(f2tf32(f)); }
__device__ __forceinline__ void mma_tf32(float* c, const uint32_t* a, const uint32_t* b) {
    asm volatile(
        "mma.sync.aligned.m16n8k8.row.col.f32.tf32.tf32.f32 "
        "{%0,%1,%2,%3}, {%4,%5,%6,%7}, {%8,%9}, {%0,%1,%2,%3};"
        : "+f"(c[0]), "+f"(c[1]), "+f"(c[2]), "+f"(c[3])
        : "r"(a[0]), "r"(a[1]), "r"(a[2]), "r"(a[3]), "r"(b[0]), "r"(b[1]));
}
__device__ __forceinline__ uint32_t smem_u32(const void* p) {
    uint32_t a;
    asm("{ .reg .u64 t; cvta.to.shared.u64 t, %1; cvt.u32.u64 %0, t; }" : "=r"(a) : "l"(p));
    return a;
}
#define CP_ASYNC16(dst, src) \
    asm volatile("cp.async.cg.shared.global [%0], [%1], 16;" \
        :: "r"(dst), "l"(__cvta_generic_to_global(src)) : "memory")
#define CP_COMMIT() asm volatile("cp.async.commit_group;" ::: "memory")
#define CP_WAIT(n)  asm volatile("cp.async.wait_group %0;" :: "n"(n) : "memory")

// ===========================================================================
// Weight prep: transposes + fused/padded off-mask weight; ALL tf32-rounded.
// ===========================================================================
__global__ void prep_weights_kernel(const float* __restrict__ w0, const float* __restrict__ w1,
                                    const float* __restrict__ w3,
                                    const float* __restrict__ offw, const float* __restrict__ maskw,
                                    const float* __restrict__ offb, const float* __restrict__ maskb,
                                    float* __restrict__ w0R, float* __restrict__ w1T,
                                    float* __restrict__ w3T,
                                    float* __restrict__ w2P, float* __restrict__ b2) {
    const int n = blockIdx.x, k = threadIdx.x;
    w0R[n * CC + k] = tf32r(w0[n * CC + k]);     // conv_w already [co][ci]
    w1T[n * CC + k] = tf32r(w1[k * CC + n]);
    w3T[n * CC + k] = tf32r(w3[k * CC + n]);
    float v = 0.f;
    if (n < 72)       v = offw[k * 72 + n];
    else if (n < 108) v = maskw[k * 36 + (n - 72)];
    w2P[n * CC + k] = tf32r(v);
    if (k == 0) b2[n] = (n < 72) ? offb[n] : ((n < 108) ? maskb[n - 72] : 0.f);
}

// ===========================================================================
// x NCHW -> NHWC with 1-px zero border; tf32-rounded (GEMM-A source).
// ===========================================================================
__global__ void pack_x_kernel(const float* __restrict__ x, float* __restrict__ xt) {
    __shared__ float t[32][33];
    const int b  = blockIdx.z >> 6;
    const int h  = blockIdx.z & 63;
    const int w0 = blockIdx.x * 32;
    const int c0 = blockIdx.y * 32;
    const int tx = threadIdx.x, ty = threadIdx.y;
    const int hh = h - 1;
    const int ww = w0 + tx - 1;
    const int cc = c0 + ty;
    float v = 0.f;
    if (hh >= 0 && hh < HIN && ww >= 0 && ww < HIN)
        v = x[(((size_t)b * CC + cc) * HIN + hh) * HIN + ww];
    t[ty][tx] = v;
    __syncthreads();
    xt[(((size_t)b * HH + h) * WW + (w0 + ty)) * CC + (c0 + tx)] = tf32r(t[tx][ty]);
}

// ===========================================================================
// HMMA tf32 GEMM, split-N + cp.async double-buffered K-chunks.
// ALL operands pre-rounded to tf32 -> inner loop is pure LDS + MMA (no cvt).
// CTA = 256 threads (4m x 2n warps); tile = 128 rows x 64 cols; K chunk = 64.
// TO_NCHW: epilogue transposes to NCHW. ROUND_OUT: round C to tf32 (feeds GEMM).
// ===========================================================================
#define CH      64
#define CPITCH  68
#define STAGE_F (192 * CPITCH)
#define GEMM_SMEM (2 * STAGE_F * 4)       // 104448 bytes
#define SPITCH  132

template <bool TO_NCHW, bool ROUND_OUT>
__global__ void __launch_bounds__(256, 2)
hmma_gemm_kernel(const float* __restrict__ A, const float* __restrict__ Bm,
                 const float* __restrict__ bias, float* __restrict__ Cout) {
    extern __shared__ float smem[];
    const uint32_t sbase = smem_u32(smem);

    const int tid  = threadIdx.x;
    const int lane = tid & 31;
    const int wid  = tid >> 5;
    const int gid  = lane >> 2;
    const int tg   = lane & 3;
    const int warp_m = wid & 3;
    const int warp_n = wid >> 2;
    const int m0 = blockIdx.x * 128;
    const int n0 = blockIdx.y * 64;

    const int irow_a = tid >> 4;
    const int ic     = (tid & 15) * 4;
    auto issue = [&](int s, int kc) {
        const uint32_t st = sbase + (uint32_t)(s * STAGE_F * 4);
        #pragma unroll
        for (int i = 0; i < 8; i++) {
            const int row = irow_a + i * 16;
            CP_ASYNC16(st + (uint32_t)((row * CPITCH + ic) * 4),
                       A + (size_t)(m0 + row) * CC + kc + ic);
        }
        #pragma unroll
        for (int i = 0; i < 4; i++) {
            const int row = irow_a + i * 16;
            if (row < 64) {
                CP_ASYNC16(st + (uint32_t)(((128 + row) * CPITCH + ic) * 4),
                           Bm + (size_t)(n0 + row) * CC + kc + ic);
            }
        }
        CP_COMMIT();
    };

    issue(0, 0);
    issue(1, CH);

    float acc[2][4][4];
    #pragma unroll
    for (int mi = 0; mi < 2; mi++)
        #pragma unroll
        for (int ni = 0; ni < 4; ni++)
            #pragma unroll
            for (int j = 0; j < 4; j++) acc[mi][ni][j] = 0.f;

    const int arow0 = warp_m * 32 + gid;
    const int bcol0 = warp_n * 32 + gid;

    auto mma_chunk = [&](int s) {
        const uint32_t* uA = reinterpret_cast<const uint32_t*>(smem + s * STAGE_F);
        const uint32_t* uB = uA + 128 * CPITCH;
        #pragma unroll
        for (int ks = 0; ks < 8; ks++) {
            const int k8 = ks * 8;
            uint32_t af[2][4];
            #pragma unroll
            for (int mi = 0; mi < 2; mi++) {
                const int r = arow0 + mi * 16;
                af[mi][0] = uA[(r    ) * CPITCH + k8 + tg];
                af[mi][1] = uA[(r + 8) * CPITCH + k8 + tg];
                af[mi][2] = uA[(r    ) * CPITCH + k8 + tg + 4];
                af[mi][3] = uA[(r + 8) * CPITCH + k8 + tg + 4];
            }
            #pragma unroll
            for (int ni = 0; ni < 4; ni++) {
                const int n = bcol0 + ni * 8;
                uint32_t bf[2];
                bf[0] = uB[n * CPITCH + k8 + tg];
                bf[1] = uB[n * CPITCH + k8 + tg + 4];
                mma_tf32(acc[0][ni], af[0], bf);
                mma_tf32(acc[1][ni], af[1], bf);
            }
        }
    };

    CP_WAIT(1);
    __syncthreads();
    mma_chunk(0);
    CP_WAIT(0);
    __syncthreads();
    mma_chunk(1);

    float2 bb[4];
    #pragma unroll
    for (int ni = 0; ni < 4; ni++) {
        const int col = n0 + warp_n * 32 + ni * 8 + 2 * tg;
        bb[ni].x = __ldg(bias + col);
        bb[ni].y = __ldg(bias + col + 1);
    }

    auto post = [&](float v) { return ROUND_OUT ? tf32r(v) : v; };

    if (!TO_NCHW) {
        #pragma unroll
        for (int mi = 0; mi < 2; mi++) {
            const int r0 = m0 + arow0 + mi * 16;
            #pragma unroll
            for (int ni = 0; ni < 4; ni++) {
                const int col = n0 + warp_n * 32 + ni * 8 + 2 * tg;
                float2 v0 = make_float2(post(acc[mi][ni][0] + bb[ni].x), post(acc[mi][ni][1] + bb[ni].y));
                float2 v1 = make_float2(post(acc[mi][ni][2] + bb[ni].x), post(acc[mi][ni][3] + bb[ni].y));
                *reinterpret_cast<float2*>(Cout + (size_t)r0 * CC + col)       = v0;
                *reinterpret_cast<float2*>(Cout + (size_t)(r0 + 8) * CC + col) = v1;
            }
        }
    } else {
        __syncthreads();
        float* sCT = smem;  // [64 cols][128 rows], pitch 132
        #pragma unroll
        for (int mi = 0; mi < 2; mi++) {
            #pragma unroll
            for (int ni = 0; ni < 4; ni++) {
                const int col = warp_n * 32 + ni * 8 + 2 * tg;
                const int r   = arow0 + mi * 16;
                sCT[(col    ) * SPITCH + r    ] = acc[mi][ni][0] + bb[ni].x;
                sCT[(col + 1) * SPITCH + r    ] = acc[mi][ni][1] + bb[ni].y;
                sCT[(col    ) * SPITCH + r + 8] = acc[mi][ni][2] + bb[ni].x;
                sCT[(col + 1) * SPITCH + r + 8] = acc[mi][ni][3] + bb[ni].y;
            }
        }
        __syncthreads();
        const int b       = m0 >> 12;
        const int inbatch = m0 & 4095;
        #pragma unroll
        for (int i = 0; i < 8; i++) {
            const int idx = i * 256 + tid;
            const int col = idx >> 5;
            const int rc  = idx & 31;
            const float4 v = *reinterpret_cast<const float4*>(sCT + col * SPITCH + rc * 4);
            *reinterpret_cast<float4*>(
                Cout + ((size_t)b * CC + (n0 + col)) * (HH * WW) + inbatch + rc * 4) = v;
        }
    }
}

// ===========================================================================
// Depthwise 3x3 (pad 1) + bias + LayerNorm(C) + exact GELU; tf32-rounded out.
// ===========================================================================
__global__ void __launch_bounds__(256)
dw_ln_gelu_kernel(const float* __restrict__ y,
                  const float* __restrict__ dww,
                  const float* __restrict__ dwb,
                  const float* __restrict__ lng,
                  const float* __restrict__ lnb,
                  float* __restrict__ out) {
    __shared__ float sW[9 * CC];
    const int tid = threadIdx.x;
    for (int i = tid; i < 9 * CC; i += 256) {
        const int c = i / 9, tap = i % 9;
        sW[tap * CC + c] = dww[i];
    }
    __syncthreads();

    const int wid  = tid >> 5;
    const int lane = tid & 31;
    const int pos  = blockIdx.x * 8 + wid;
    const int b = pos >> 12;
    const int h = (pos >> 6) & 63;
    const int w = pos & 63;
    const int c4 = lane * 4;

    const float4 bv = __ldg(reinterpret_cast<const float4*>(dwb + c4));
    float4 acc = bv;
    const float* ybase = y + (((size_t)b * HH + h) * WW + w) * CC + c4;
    #pragma unroll
    for (int i = 0; i < 3; i++) {
        const int hh = h + i - 1;
        if ((unsigned)hh >= (unsigned)HH) continue;
        #pragma unroll
        for (int j = 0; j < 3; j++) {
            const int ww = w + j - 1;
            if ((unsigned)ww >= (unsigned)WW) continue;
            const float4 v = __ldg(reinterpret_cast<const float4*>(
                ybase + ((i - 1) * WW + (j - 1)) * CC));
            const float4 wt = *reinterpret_cast<const float4*>(sW + (i * 3 + j) * CC + c4);
            acc.x = fmaf(v.x, wt.x, acc.x);
            acc.y = fmaf(v.y, wt.y, acc.y);
            acc.z = fmaf(v.z, wt.z, acc.z);
            acc.w = fmaf(v.w, wt.w, acc.w);
        }
    }

    float s  = acc.x + acc.y + acc.z + acc.w;
    float s2 = acc.x * acc.x + acc.y * acc.y + acc.z * acc.z + acc.w * acc.w;
    #pragma unroll
    for (int o = 16; o > 0; o >>= 1) {
        s  += __shfl_xor_sync(0xFFFFFFFFu, s,  o);
        s2 += __shfl_xor_sync(0xFFFFFFFFu, s2, o);
    }
    const float mean = s * (1.f / CC);
    const float var  = s2 * (1.f / CC) - mean * mean;
    const float rstd = rsqrtf(var + 1e-5f);

    const float4 gv = __ldg(reinterpret_cast<const float4*>(lng + c4));
    const float4 betav = __ldg(reinterpret_cast<const float4*>(lnb + c4));
    float4 o4;
    {
        float v0 = (acc.x - mean) * rstd * gv.x + betav.x;
        float v1 = (acc.y - mean) * rstd * gv.y + betav.y;
        float v2 = (acc.z - mean) * rstd * gv.z + betav.z;
        float v3 = (acc.w - mean) * rstd * gv.w + betav.w;
        const float k = 0.70710678118654752440f;
        o4.x = tf32r(0.5f * v0 * (1.f + erff(v0 * k)));
        o4.y = tf32r(0.5f * v1 * (1.f + erff(v1 * k)));
        o4.z = tf32r(0.5f * v2 * (1.f + erff(v2 * k)));
        o4.w = tf32r(0.5f * v3 * (1.f + erff(v3 * k)));
    }
    *reinterpret_cast<float4*>(out + (size_t)pos * CC + c4) = o4;
}

// ===========================================================================
// DCNv3 bilinear sampler + fused group softmax; tf32-rounded out (GEMM-A).
// ===========================================================================
__global__ void __launch_bounds__(256)
sampler_kernel(const float* __restrict__ xproj,
               const float* __restrict__ om,
               float* __restrict__ out) {
    __shared__ float sOM[8][112];
    const int tid  = threadIdx.x;
    const int wid  = tid >> 5;
    const int lane = tid & 31;
    const int pos  = blockIdx.x * 8 + wid;
    const int b = pos >> 12;
    const int h = (pos >> 6) & 63;
    const int w = pos & 63;
    const int g  = lane >> 3;
    const int c4 = (lane & 7) * 4;

    #pragma unroll
    for (int r = 0; r < 4; r++) {
        const int i = r * 32 + lane;
        if (i < 108) sOM[wid][i] = __ldg(om + (size_t)pos * CC + i);
    }
    __syncwarp();

    const float* logit = &sOM[wid][72 + g * 9];
    float mx = -1e30f;
    #pragma unroll
    for (int p = 0; p < 9; p++) mx = fmaxf(mx, logit[p]);
    float se = 0.f;
    float ex[9];
    #pragma unroll
    for (int p = 0; p < 9; p++) { ex[p] = expf(logit[p] - mx); se += ex[p]; }
    const float inv_se = 1.f / se;

    const float* base = xproj + (size_t)b * (HH * WW * CC) + g * GCC + c4;
    float4 acc = make_float4(0.f, 0.f, 0.f, 0.f);
    #pragma unroll
    for (int p = 0; p < PP; p++) {
        const int gp = g * 9 + p;
        const float fix = (float)(w + p / 3) + sOM[wid][2 * gp];
        const float fiy = (float)(h + p % 3) + sOM[wid][2 * gp + 1];
        const float x0f = floorf(fix), y0f = floorf(fiy);
        const float fx = fix - x0f, fy = fiy - y0f;
        const int x0 = (int)x0f, y0 = (int)y0f;
        const float m = ex[p] * inv_se;

        const bool xv0 = (x0 >= 1) && (x0 <= 64);
        const bool xv1 = (x0 >= 0) && (x0 <= 63);
        const bool yv0 = (y0 >= 1) && (y0 <= 64);
        const bool yv1 = (y0 >= 0) && (y0 <= 63);
        float4 v00 = make_float4(0,0,0,0), v10 = v00, v01 = v00, v11 = v00;
        if (yv0 && xv0) v00 = __ldg(reinterpret_cast<const float4*>(base + ((size_t)(y0 - 1) * WW + (x0 - 1)) * CC));
        if (yv0 && xv1) v10 = __ldg(reinterpret_cast<const float4*>(base + ((size_t)(y0 - 1) * WW + (x0    )) * CC));
        if (yv1 && xv0) v01 = __ldg(reinterpret_cast<const float4*>(base + ((size_t)(y0    ) * WW + (x0 - 1)) * CC));
        if (yv1 && xv1) v11 = __ldg(reinterpret_cast<const float4*>(base + ((size_t)(y0    ) * WW + (x0    )) * CC));

        const float w00 = (1.f - fx) * (1.f - fy) * m;
        const float w10 = fx * (1.f - fy) * m;
        const float w01 = (1.f - fx) * fy * m;
        const float w11 = fx * fy * m;
        acc.x += v00.x * w00 + v10.x * w10 + v01.x * w01 + v11.x * w11;
        acc.y += v00.y * w00 + v10.y * w10 + v01.y * w01 + v11.y * w11;
        acc.z += v00.z * w00 + v10.z * w10 + v01.z * w01 + v11.z * w11;
        acc.w += v00.w * w00 + v10.w * w10 + v01.w * w01 + v11.w * w11;
    }
    float4 o4;
    o4.x = tf32r(acc.x); o4.y = tf32r(acc.y); o4.z = tf32r(acc.z); o4.w = tf32r(acc.w);
    *reinterpret_cast<float4*>(out + (size_t)pos * CC + g * GCC + c4) = o4;
}

// ===========================================================================
extern "C" void kernel_launch(void* const* d_in, const int* in_sizes, int n_in,
                              void* d_out, int out_size) {
    const float* x         = (const float*)d_in[0];
    const float* conv_w    = (const float*)d_in[1];
    const float* conv_b    = (const float*)d_in[2];
    const float* in_proj_w = (const float*)d_in[3];
    const float* in_proj_b = (const float*)d_in[4];
    const float* dw_w      = (const float*)d_in[5];
    const float* dw_b      = (const float*)d_in[6];
    const float* ln_g      = (const float*)d_in[7];
    const float* ln_b      = (const float*)d_in[8];
    const float* off_w     = (const float*)d_in[9];
    const float* off_b     = (const float*)d_in[10];
    const float* mask_w    = (const float*)d_in[11];
    const float* mask_b    = (const float*)d_in[12];
    const float* out_w     = (const float*)d_in[13];
    const float* out_b     = (const float*)d_in[14];
    float* out = (float*)d_out;

    float *xt, *y, *xproj, *dg, *samp, *omp, *w0R, *w1T, *w2P, *w3T, *b2;
    cudaGetSymbolAddress((void**)&xt,    g_xt);
    cudaGetSymbolAddress((void**)&y,     g_y);
    cudaGetSymbolAddress((void**)&xproj, g_xproj);
    cudaGetSymbolAddress((void**)&dg,    g_dg);
    cudaGetSymbolAddress((void**)&samp,  g_samp);
    cudaGetSymbolAddress((void**)&omp,   g_om);
    cudaGetSymbolAddress((void**)&w0R,   g_w0R);
    cudaGetSymbolAddress((void**)&w1T,   g_w1T);
    cudaGetSymbolAddress((void**)&w2P,   g_w2P);
    cudaGetSymbolAddress((void**)&w3T,   g_w3T);
    cudaGetSymbolAddress((void**)&b2,    g_b2);

    static cudaStream_t s1 = nullptr;
    static cudaEvent_t eFork = nullptr, ePrep = nullptr, eConv = nullptr, eProj = nullptr;
    static bool init_done = false;
    if (!init_done) {
        cudaFuncSetAttribute((const void*)hmma_gemm_kernel<false, true>,
                             cudaFuncAttributeMaxDynamicSharedMemorySize, GEMM_SMEM);
        cudaFuncSetAttribute((const void*)hmma_gemm_kernel<false, false>,
                             cudaFuncAttributeMaxDynamicSharedMemorySize, GEMM_SMEM);
        cudaFuncSetAttribute((const void*)hmma_gemm_kernel<true, false>,
                             cudaFuncAttributeMaxDynamicSharedMemorySize, GEMM_SMEM);
        cudaStreamCreateWithFlags(&s1, cudaStreamNonBlocking);
        cudaEventCreateWithFlags(&eFork, cudaEventDisableTiming);
        cudaEventCreateWithFlags(&ePrep, cudaEventDisableTiming);
        cudaEventCreateWithFlags(&eConv, cudaEventDisableTiming);
        cudaEventCreateWithFlags(&eProj, cudaEventDisableTiming);
        init_done = true;
    }

    const dim3 tblk(32, 32);
    const dim3 tgrid(2, 4, BB * HH);
    const dim3 ggrid(NPOS / 128, 2);

    // ---- fork side stream ----
    cudaEventRecord(eFork, 0);
    cudaStreamWaitEvent(s1, eFork, 0);

    // s1: weight prep (rounded weights; conv now depends on it too)
    prep_weights_kernel<<<CC, CC, 0, s1>>>(conv_w, in_proj_w, out_w, off_w, mask_w,
                                           off_b, mask_b, w0R, w1T, w3T, w2P, b2);
    cudaEventRecord(ePrep, s1);

    // s0: pack (rounds xt) ; conv waits for prep (overlapped with pack)
    pack_x_kernel<<<tgrid, tblk>>>(x, xt);
    cudaStreamWaitEvent(0, ePrep, 0);
    hmma_gemm_kernel<false, true><<<ggrid, 256, GEMM_SMEM>>>(xt, w0R, conv_b, y);
    cudaEventRecord(eConv, 0);

    // s1: in_proj (full fp32 out; parallel with dw branch)
    cudaStreamWaitEvent(s1, eConv, 0);
    hmma_gemm_kernel<false, false><<<ggrid, 256, GEMM_SMEM, s1>>>(y, w1T, in_proj_b, xproj);
    cudaEventRecord(eProj, s1);

    // s0: dw+LN+GELU (rounds dg) -> off_mask GEMM (full fp32 out)
    dw_ln_gelu_kernel<<<NPOS / 8, 256>>>(y, dw_w, dw_b, ln_g, ln_b, dg);
    hmma_gemm_kernel<false, false><<<ggrid, 256, GEMM_SMEM>>>(dg, w2P, b2, omp);

    // join: sampler needs xproj (s1) + omp (s0); rounds samp
    cudaStreamWaitEvent(0, eProj, 0);
    sampler_kernel<<<NPOS / 8, 256>>>(xproj, omp, samp);

    // out_proj writes NCHW directly (full fp32)
    hmma_gemm_kernel<true, false><<<ggrid, 256, GEMM_SMEM>>>(samp, w3T, out_b, out);
}